// round 14
// baseline (speedup 1.0000x reference)
#include <cuda_runtime.h>
#include <cuda_bf16.h>
#include <cuda_fp16.h>
#include <mma.h>
#include <math.h>
#include <stdint.h>

using namespace nvcuda;

#define B_ 8
#define T_ 128
#define S_ 256
#define H_ 512

// scratch
__device__ __half g_hsh[B_ * S_ * H_];               // 2 MB  hs in fp16
__device__ float g_ppq[2][B_ * T_ * H_];             // 4 MB  qs split-K partials
__device__ float g_pph[2][B_ * S_ * H_];             // 8 MB  hs split-K partials
__device__ float g_po[4][B_ * T_ * H_];              // 8 MB  out split-K partials
// bf16 hi/lo pre-split operands
__device__ __nv_bfloat16 g_qhi[B_ * T_ * H_],  g_qlo[B_ * T_ * H_];
__device__ __nv_bfloat16 g_ehi[B_ * S_ * H_],  g_elo[B_ * S_ * H_];
__device__ __nv_bfloat16 g_wshi[H_ * H_],      g_wslo[H_ * H_];
__device__ __nv_bfloat16 g_whhi[H_ * H_],      g_whlo[H_ * H_];
__device__ __nv_bfloat16 g_wohi[H_ * 2 * H_],  g_wolo[H_ * 2 * H_];
__device__ __nv_bfloat16 g_chi[B_ * T_ * H_],  g_clo[B_ * T_ * H_];

// ---------------------------------------------------------------------------
__device__ __forceinline__ void bsplit(float x, __nv_bfloat16& hi, __nv_bfloat16& lo) {
    hi = __float2bfloat16(x);
    lo = __float2bfloat16(x - __bfloat162float(hi));
}
__device__ __forceinline__ uint32_t smem_u32(const void* p) {
    uint32_t a;
    asm("{ .reg .u64 t; cvta.to.shared.u64 t, %1; cvt.u32.u64 %0, t; }"
        : "=r"(a) : "l"(p));
    return a;
}
__device__ __forceinline__ void cpa16(uint32_t d, const void* s) {
    asm volatile("cp.async.cg.shared.global [%0], [%1], 16;" :: "r"(d), "l"(s));
}
#define CP_COMMIT() asm volatile("cp.async.commit_group;" ::: "memory")
#define CP_WAIT1()  asm volatile("cp.async.wait_group 1;" ::: "memory")
#define CP_WAIT0()  asm volatile("cp.async.wait_group 0;" ::: "memory")

__device__ __forceinline__ __half2 tanh2(__half2 x) {
    __half2 r;
    asm("tanh.approx.f16x2 %0, %1;"
        : "=r"(*reinterpret_cast<uint32_t*>(&r))
        : "r"(*reinterpret_cast<const uint32_t*>(&x)));
    return r;
}

// ---------------------------------------------------------------------------
// convert: split inputs + weights into bf16 hi/lo (one float4 per thread)
// ---------------------------------------------------------------------------
__global__ void __launch_bounds__(256) convert_kernel(
    const float* __restrict__ query, const float* __restrict__ enc,
    const float* __restrict__ W_s, const float* __restrict__ W_h,
    const float* __restrict__ W_out)
{
    const int i4 = blockIdx.x * 256 + threadIdx.x;
    const float* src;
    __nv_bfloat16 *dhi, *dlo;
    int off;
    if (i4 < 131072)      { src = query; dhi = g_qhi;  dlo = g_qlo;  off = i4; }
    else if (i4 < 393216) { src = enc;   dhi = g_ehi;  dlo = g_elo;  off = i4 - 131072; }
    else if (i4 < 458752) { src = W_s;   dhi = g_wshi; dlo = g_wslo; off = i4 - 393216; }
    else if (i4 < 524288) { src = W_h;   dhi = g_whhi; dlo = g_whlo; off = i4 - 458752; }
    else                  { src = W_out; dhi = g_wohi; dlo = g_wolo; off = i4 - 524288; }

    const float4 v = reinterpret_cast<const float4*>(src)[off];
    union { __nv_bfloat16 h[4]; uint2 u; } ph, pl;
    bsplit(v.x, ph.h[0], pl.h[0]); bsplit(v.y, ph.h[1], pl.h[1]);
    bsplit(v.z, ph.h[2], pl.h[2]); bsplit(v.w, ph.h[3], pl.h[3]);
    reinterpret_cast<uint2*>(dhi)[off] = ph.u;
    reinterpret_cast<uint2*>(dlo)[off] = pl.u;
}

// ---------------------------------------------------------------------------
// Split-K wmma GEMM (bf16 3-term compensation), fp32 partial output.
// Tile 64x64, 256 threads, 8 warps (warp tile 16x32), K-chunk 32, 2-stage.
// ---------------------------------------------------------------------------
#define PITCH 40
#define TILE_B (64 * PITCH * 2)          // 5120 B
#define AHI_O 0
#define ALO_O (TILE_B)
#define BHI_O (2 * TILE_B)
#define BLO_O (3 * TILE_B)
#define BUF_B (4 * TILE_B)               // 20480 B per stage
#define SMEM_BYTES (2 * BUF_B)           // 40960 B

__device__ __forceinline__ void issue_chunk(
    uint32_t sb,
    const __nv_bfloat16* __restrict__ Ahi, const __nv_bfloat16* __restrict__ Alo,
    const __nv_bfloat16* __restrict__ Bhi, const __nv_bfloat16* __restrict__ Blo,
    int ldb, int m0, int n0, int aoff, int boff, int tid)
{
    const int row = tid >> 2, seg = tid & 3;       // 64 rows x 4 x 16B
    const uint32_t soff = (uint32_t)(row * (PITCH * 2) + seg * 16);
    const size_t ao = (size_t)(m0 + row) * H_ + aoff + seg * 8;
    const size_t bo = (size_t)(n0 + row) * ldb + boff + seg * 8;
    cpa16(sb + AHI_O + soff, Ahi + ao);
    cpa16(sb + ALO_O + soff, Alo + ao);
    cpa16(sb + BHI_O + soff, Bhi + bo);
    cpa16(sb + BLO_O + soff, Blo + bo);
}

__device__ __forceinline__ void gemm_sk(
    char* smem,
    const __nv_bfloat16* __restrict__ Ahi, const __nv_bfloat16* __restrict__ Alo,
    const __nv_bfloat16* __restrict__ Bhi, const __nv_bfloat16* __restrict__ Blo,
    int ldb, float* __restrict__ Cpart,
    int m0, int n0, int akbeg, int bkbeg, int nchunks)
{
    const int tid  = threadIdx.x;
    const int wid  = tid >> 5;
    const int m0w  = (wid >> 1) * 16;    // 4 m-warps x 16 rows
    const int n0w  = (wid & 1) * 32;     // 2 n-warps x 32 cols
    const uint32_t sb = smem_u32(smem);

    wmma::fragment<wmma::accumulator, 16, 16, 16, float> acc[2];
    wmma::fill_fragment(acc[0], 0.0f);
    wmma::fill_fragment(acc[1], 0.0f);

    issue_chunk(sb, Ahi, Alo, Bhi, Blo, ldb, m0, n0, akbeg, bkbeg, tid);
    CP_COMMIT();

    #pragma unroll 1
    for (int it = 0; it < nchunks; ++it) {
        if (it + 1 < nchunks) {
            issue_chunk(sb + ((it + 1) & 1) * BUF_B, Ahi, Alo, Bhi, Blo,
                        ldb, m0, n0, akbeg + (it + 1) * 32, bkbeg + (it + 1) * 32, tid);
            CP_COMMIT();
            CP_WAIT1();
        } else {
            CP_WAIT0();
        }
        __syncthreads();

        const char* buf = smem + (it & 1) * BUF_B;
        const __nv_bfloat16* sAhi = reinterpret_cast<const __nv_bfloat16*>(buf + AHI_O);
        const __nv_bfloat16* sAlo = reinterpret_cast<const __nv_bfloat16*>(buf + ALO_O);
        const __nv_bfloat16* sBhi = reinterpret_cast<const __nv_bfloat16*>(buf + BHI_O);
        const __nv_bfloat16* sBlo = reinterpret_cast<const __nv_bfloat16*>(buf + BLO_O);

        #pragma unroll
        for (int kf = 0; kf < 2; kf++) {
            const int ko = kf * 16;
            wmma::fragment<wmma::matrix_a, 16, 16, 16, __nv_bfloat16, wmma::row_major> ahi, alo;
            wmma::fragment<wmma::matrix_b, 16, 16, 16, __nv_bfloat16, wmma::col_major> bhi[2], blo[2];
            wmma::load_matrix_sync(ahi, &sAhi[m0w * PITCH + ko], PITCH);
            wmma::load_matrix_sync(alo, &sAlo[m0w * PITCH + ko], PITCH);
            #pragma unroll
            for (int ni = 0; ni < 2; ni++) {
                wmma::load_matrix_sync(bhi[ni], &sBhi[(n0w + 16 * ni) * PITCH + ko], PITCH);
                wmma::load_matrix_sync(blo[ni], &sBlo[(n0w + 16 * ni) * PITCH + ko], PITCH);
            }
            #pragma unroll
            for (int ni = 0; ni < 2; ni++) {
                wmma::mma_sync(acc[ni], ahi, bhi[ni], acc[ni]);
                wmma::mma_sync(acc[ni], ahi, blo[ni], acc[ni]);
                wmma::mma_sync(acc[ni], alo, bhi[ni], acc[ni]);
            }
        }
        __syncthreads();
    }

    #pragma unroll
    for (int ni = 0; ni < 2; ni++)
        wmma::store_matrix_sync(
            &Cpart[(size_t)(m0 + m0w) * H_ + n0 + n0w + 16 * ni],
            acc[ni], H_, wmma::mem_row_major);
}

// proj: grid (8, 48, 2). y<16 -> qs partial; else hs partial. kz splits K=512 in 2.
__global__ void __launch_bounds__(256) proj_wmma()
{
    __shared__ __align__(16) char smem[SMEM_BYTES];
    const int n0 = blockIdx.x * 64;
    const int my = blockIdx.y;
    const int kz = blockIdx.z;
    const int kb = kz * 256;
    if (my < 16)
        gemm_sk(smem, g_qhi, g_qlo, g_wshi, g_wslo, H_,
                g_ppq[kz], my * 64, n0, kb, kb, 8);
    else
        gemm_sk(smem, g_ehi, g_elo, g_whhi, g_whlo, H_,
                g_pph[kz], (my - 16) * 64, n0, kb, kb, 8);
}

// preduce: hs = fp16(pph0+pph1)  (262144 float4s -> 1024 blocks)
__global__ void __launch_bounds__(256) preduce_kernel()
{
    const int j = blockIdx.x * 256 + threadIdx.x;
    const float4 a = reinterpret_cast<const float4*>(g_pph[0])[j];
    const float4 b = reinterpret_cast<const float4*>(g_pph[1])[j];
    const __half2 h0 = __floats2half2_rn(a.x + b.x, a.y + b.y);
    const __half2 h1 = __floats2half2_rn(a.z + b.z, a.w + b.w);
    uint2 st;
    st.x = *reinterpret_cast<const uint32_t*>(&h0);
    st.y = *reinterpret_cast<const uint32_t*>(&h1);
    reinterpret_cast<uint2*>(g_hsh)[j] = st;
}

// out: grid (8, 16, 4). kz<2 reads ctx, kz>=2 reads query (concat-aligned split-K).
__global__ void __launch_bounds__(256) out_wmma()
{
    __shared__ __align__(16) char smem[SMEM_BYTES];
    const int kz = blockIdx.z;
    const __nv_bfloat16* Ahi = (kz < 2) ? g_chi : g_qhi;
    const __nv_bfloat16* Alo = (kz < 2) ? g_clo : g_qlo;
    gemm_sk(smem, Ahi, Alo, g_wohi, g_wolo, 2 * H_,
            g_po[kz], blockIdx.y * 64, blockIdx.x * 64,
            (kz & 1) * 256, kz * 256, 8);
}

// oreduce: out = tanh(p0+p1+p2+p3 + bias)  (131072 float4s -> 512 blocks)
__global__ void __launch_bounds__(256) oreduce_kernel(
    const float* __restrict__ bias, float* __restrict__ out)
{
    const int i4 = blockIdx.x * 256 + threadIdx.x;
    const float4 p0 = reinterpret_cast<const float4*>(g_po[0])[i4];
    const float4 p1 = reinterpret_cast<const float4*>(g_po[1])[i4];
    const float4 p2 = reinterpret_cast<const float4*>(g_po[2])[i4];
    const float4 p3 = reinterpret_cast<const float4*>(g_po[3])[i4];
    const float4 bb = *reinterpret_cast<const float4*>(&bias[(i4 & 127) * 4]);
    float4 o;
    o.x = tanhf(p0.x + p1.x + p2.x + p3.x + bb.x);
    o.y = tanhf(p0.y + p1.y + p2.y + p3.y + bb.y);
    o.z = tanhf(p0.z + p1.z + p2.z + p3.z + bb.z);
    o.w = tanhf(p0.w + p1.w + p2.w + p3.w + bb.w);
    reinterpret_cast<float4*>(out)[i4] = o;
}

// ---------------------------------------------------------------------------
// Fused attention, TT=4, 512 threads, 256 blocks, 2 CTAs/SM.
// Pass1 packed fp16, SC=16: each warp owns 4 rows per chunk so the 4
// shfl-reduce chains overlap and barrier count halves (<=16 syncs).
// Scores transposed [S][TT]; pass2 fp32. qreg fuses qs split-K add.
// smem: 32KB (fp16 hs double buffer) + 4KB scores = 36KB, 2 CTAs/SM.
// ---------------------------------------------------------------------------
#define TT 4
#define SC 16

__global__ void __launch_bounds__(512, 2) attn_kernel(
    const float* __restrict__ enc, const float* __restrict__ v,
    const int* __restrict__ lens)
{
    __shared__ __align__(16) __half sh_hs[2][SC * H_];   // 2 x 16 KB
    __shared__ float sh_sc[S_][TT];                      // 4 KB (transposed)
    __shared__ float sh_rsum[TT];

    const int b     = blockIdx.y;
    const int t0    = blockIdx.x * TT;
    const int tid   = threadIdx.x;
    const int lane  = tid & 31;
    const int wid   = tid >> 5;               // 0..15
    const int t_loc = wid >> 2;               // 0..3
    const int squad = wid & 3;                // 0..3

    const int len = lens[b];
    const int nch = (len + SC - 1) / SC;      // 8..16 chunks

    // q (fused split-K partial sum) + v packed to half2.
    __half2 qh[8], vh[8];
    {
        const size_t ro = (size_t)(b * T_ + t0 + t_loc) * H_;
        #pragma unroll
        for (int c = 0; c < 2; c++) {
            #pragma unroll
            for (int k2 = 0; k2 < 2; k2++) {
                const int off = c * 256 + lane * 8 + k2 * 4;
                const float4 p0 = *reinterpret_cast<const float4*>(&g_ppq[0][ro + off]);
                const float4 p1 = *reinterpret_cast<const float4*>(&g_ppq[1][ro + off]);
                const float4 vv = *reinterpret_cast<const float4*>(&v[off]);
                qh[c * 4 + k2 * 2 + 0] = __floats2half2_rn(p0.x + p1.x, p0.y + p1.y);
                qh[c * 4 + k2 * 2 + 1] = __floats2half2_rn(p0.z + p1.z, p0.w + p1.w);
                vh[c * 4 + k2 * 2 + 0] = __floats2half2_rn(vv.x, vv.y);
                vh[c * 4 + k2 * 2 + 1] = __floats2half2_rn(vv.z, vv.w);
            }
        }
    }

    const __half* hsb = g_hsh + (size_t)b * S_ * H_;
    const float* encb = enc + (size_t)b * S_ * H_;

    // ---- Pass 1: double-buffered (2 uint4 per thread per chunk) ----
    uint4 r[2];
    #pragma unroll
    for (int q = 0; q < 2; q++)
        r[q] = reinterpret_cast<const uint4*>(hsb)[q * 512 + tid];
    #pragma unroll
    for (int q = 0; q < 2; q++)
        reinterpret_cast<uint4*>(&sh_hs[0][0])[q * 512 + tid] = r[q];

    #pragma unroll 1
    for (int it = 0; it < nch; ++it) {
        if (it + 1 < nch) {
            const uint4* nxt = reinterpret_cast<const uint4*>(hsb + (size_t)(it + 1) * SC * H_);
            #pragma unroll
            for (int q = 0; q < 2; q++)
                r[q] = nxt[q * 512 + tid];
        }
        __syncthreads();   // buf[it&1] ready; all warps done with buf[(it+1)&1]

        const __half* base = sh_hs[it & 1];
        const int s0 = it * SC;
        #pragma unroll
        for (int i = 0; i < SC / 4; i++) {     // warp owns 4 of the 16 rows
            const int ro = squad * (SC / 4) + i;
            const uint4* hrow = reinterpret_cast<const uint4*>(&base[ro * H_]);
            __half2 accA = __float2half2_rn(0.0f);
            __half2 accB = __float2half2_rn(0.0f);
            #pragma unroll
            for (int c = 0; c < 2; c++) {
                const uint4 hv = hrow[c * 32 + lane];
                const __half2 h0 = *reinterpret_cast<const __half2*>(&hv.x);
                const __half2 h1 = *reinterpret_cast<const __half2*>(&hv.y);
                const __half2 h2 = *reinterpret_cast<const __half2*>(&hv.z);
                const __half2 h3 = *reinterpret_cast<const __half2*>(&hv.w);
                accA = __hfma2(tanh2(__hadd2(qh[c * 4 + 0], h0)), vh[c * 4 + 0], accA);
                accB = __hfma2(tanh2(__hadd2(qh[c * 4 + 1], h1)), vh[c * 4 + 1], accB);
                accA = __hfma2(tanh2(__hadd2(qh[c * 4 + 2], h2)), vh[c * 4 + 2], accA);
                accB = __hfma2(tanh2(__hadd2(qh[c * 4 + 3], h3)), vh[c * 4 + 3], accB);
            }
            const float2 fA = __half22float2(accA);
            const float2 fB = __half22float2(accB);
            float acc = (fA.x + fA.y) + (fB.x + fB.y);
            acc += __shfl_xor_sync(0xffffffffu, acc, 16);
            acc += __shfl_xor_sync(0xffffffffu, acc, 8);
            acc += __shfl_xor_sync(0xffffffffu, acc, 4);
            acc += __shfl_xor_sync(0xffffffffu, acc, 2);
            acc += __shfl_xor_sync(0xffffffffu, acc, 1);
            if (lane == 0) sh_sc[s0 + ro][t_loc] = acc;
        }

        if (it + 1 < nch) {
            uint4* dst = reinterpret_cast<uint4*>(&sh_hs[(it + 1) & 1][0]);
            #pragma unroll
            for (int q = 0; q < 2; q++)
                dst[q * 512 + tid] = r[q];
        }
    }
    __syncthreads();

    // ---- Softmax (warps 0-3, one per t row) ----
    if (wid < TT) {
        const int t = wid;
        float vals[S_ / 32];
        float m = -1e30f;
        #pragma unroll
        for (int i = 0; i < S_ / 32; i++) {
            const int s = lane + 32 * i;
            const float sc = (s < len) ? sh_sc[s][t] : -1e30f;
            vals[i] = sc;
            m = fmaxf(m, sc);
        }
        #pragma unroll
        for (int o = 16; o; o >>= 1) m = fmaxf(m, __shfl_xor_sync(0xffffffffu, m, o));
        float sum = 0.f;
        #pragma unroll
        for (int i = 0; i < S_ / 32; i++) {
            const int s = lane + 32 * i;
            const float e = (s < len) ? __expf(vals[i] - m) : 0.f;
            sh_sc[s][t] = e;
            sum += e;
        }
        #pragma unroll
        for (int o = 16; o; o >>= 1) sum += __shfl_xor_sync(0xffffffffu, sum, o);
        if (lane == 0) sh_rsum[t] = 1.0f / sum;
    }
    __syncthreads();

    // ---- Pass 2: context; 4 groups over s-quarters of [0,len) ----
    const int g  = tid >> 7;                  // 0..3
    const int c4 = tid & 127;
    const int sbeg = (g * len) >> 2;
    const int send = ((g + 1) * len) >> 2;

    float4 acc4[TT];
    #pragma unroll
    for (int t = 0; t < TT; t++) acc4[t] = make_float4(0.f, 0.f, 0.f, 0.f);

    #pragma unroll 4
    for (int s = sbeg; s < send; s++) {
        const float4 e4 = *reinterpret_cast<const float4*>(&encb[(size_t)s * H_ + c4 * 4]);
        const float4 w4 = *reinterpret_cast<const float4*>(&sh_sc[s][0]);
        acc4[0].x = fmaf(w4.x, e4.x, acc4[0].x);
        acc4[0].y = fmaf(w4.x, e4.y, acc4[0].y);
        acc4[0].z = fmaf(w4.x, e4.z, acc4[0].z);
        acc4[0].w = fmaf(w4.x, e4.w, acc4[0].w);
        acc4[1].x = fmaf(w4.y, e4.x, acc4[1].x);
        acc4[1].y = fmaf(w4.y, e4.y, acc4[1].y);
        acc4[1].z = fmaf(w4.y, e4.z, acc4[1].z);
        acc4[1].w = fmaf(w4.y, e4.w, acc4[1].w);
        acc4[2].x = fmaf(w4.z, e4.x, acc4[2].x);
        acc4[2].y = fmaf(w4.z, e4.y, acc4[2].y);
        acc4[2].z = fmaf(w4.z, e4.z, acc4[2].z);
        acc4[2].w = fmaf(w4.z, e4.w, acc4[2].w);
        acc4[3].x = fmaf(w4.w, e4.x, acc4[3].x);
        acc4[3].y = fmaf(w4.w, e4.y, acc4[3].y);
        acc4[3].z = fmaf(w4.w, e4.z, acc4[3].z);
        acc4[3].w = fmaf(w4.w, e4.w, acc4[3].w);
    }

    // combine via smem (reuse fp16 buffers as float scratch: 8KB needed each)
    float* bufA = reinterpret_cast<float*>(&sh_hs[0][0]);
    float* bufB = reinterpret_cast<float*>(&sh_hs[1][0]);
    if (g == 1) {
        #pragma unroll
        for (int t = 0; t < TT; t++)
            *reinterpret_cast<float4*>(&bufA[(t * 128 + c4) * 4]) = acc4[t];
    }
    if (g == 3) {
        #pragma unroll
        for (int t = 0; t < TT; t++)
            *reinterpret_cast<float4*>(&bufB[(t * 128 + c4) * 4]) = acc4[t];
    }
    __syncthreads();
    if (g == 0) {
        #pragma unroll
        for (int t = 0; t < TT; t++) {
            const float4 p = *reinterpret_cast<const float4*>(&bufA[(t * 128 + c4) * 4]);
            acc4[t].x += p.x; acc4[t].y += p.y; acc4[t].z += p.z; acc4[t].w += p.w;
        }
    }
    if (g == 2) {
        #pragma unroll
        for (int t = 0; t < TT; t++) {
            const float4 p = *reinterpret_cast<const float4*>(&bufB[(t * 128 + c4) * 4]);
            acc4[t].x += p.x; acc4[t].y += p.y; acc4[t].z += p.z; acc4[t].w += p.w;
            *reinterpret_cast<float4*>(&bufB[(t * 128 + c4) * 4]) = acc4[t];
        }
    }
    __syncthreads();
    if (g == 0) {
        #pragma unroll
        for (int t = 0; t < TT; t++) {
            const float4 p = *reinterpret_cast<const float4*>(&bufB[(t * 128 + c4) * 4]);
            const float rs = sh_rsum[t];
            float4 o;
            o.x = (acc4[t].x + p.x) * rs;
            o.y = (acc4[t].y + p.y) * rs;
            o.z = (acc4[t].z + p.z) * rs;
            o.w = (acc4[t].w + p.w) * rs;
            union { __nv_bfloat16 h[4]; uint2 u; } ph, pl;
            bsplit(o.x, ph.h[0], pl.h[0]); bsplit(o.y, ph.h[1], pl.h[1]);
            bsplit(o.z, ph.h[2], pl.h[2]); bsplit(o.w, ph.h[3], pl.h[3]);
            const size_t off = (size_t)(b * T_ + t0 + t) * H_ + c4 * 4;
            *reinterpret_cast<uint2*>(&g_chi[off]) = ph.u;
            *reinterpret_cast<uint2*>(&g_clo[off]) = pl.u;
        }
    }
}

// ---------------------------------------------------------------------------
extern "C" void kernel_launch(void* const* d_in, const int* in_sizes, int n_in,
                              void* d_out, int out_size)
{
    const float* query = (const float*)d_in[0];
    const float* enc   = (const float*)d_in[1];
    const int*   lens  = (const int*)d_in[2];
    const float* W_s   = (const float*)d_in[3];
    const float* W_h   = (const float*)d_in[4];
    const float* v     = (const float*)d_in[5];
    const float* W_out = (const float*)d_in[6];
    const float* b_out = (const float*)d_in[7];
    float* out = (float*)d_out;

    convert_kernel<<<2560, 256>>>(query, enc, W_s, W_h, W_out);
    proj_wmma<<<dim3(8, 48, 2), 256>>>();
    preduce_kernel<<<1024, 256>>>();
    attn_kernel<<<dim3(T_ / TT, B_), 512>>>(enc, v, lens);
    out_wmma<<<dim3(8, 16, 4), 256>>>();
    oreduce_kernel<<<512, 256>>>(b_out, out);
}

// round 15
// speedup vs baseline: 1.1826x; 1.1826x over previous
#include <cuda_runtime.h>
#include <cuda_bf16.h>
#include <cuda_fp16.h>
#include <mma.h>
#include <math.h>
#include <stdint.h>

using namespace nvcuda;

#define B_ 8
#define T_ 128
#define S_ 256
#define H_ 512

// scratch
__device__ __half g_hsh[B_ * S_ * H_];               // 2 MB  hs in fp16
__device__ float g_ppq[2][B_ * T_ * H_];             // 4 MB  qs split-K partials
__device__ float g_pph[2][B_ * S_ * H_];             // 8 MB  hs split-K partials
__device__ float g_po[4][B_ * T_ * H_];              // 8 MB  out split-K partials
// fp16 operands for projection GEMMs (single product)
__device__ __half g_qf16[B_ * T_ * H_];              // 1 MB
__device__ __half g_ef16[B_ * S_ * H_];              // 2 MB
__device__ __half g_wsf16[H_ * H_];                  // 0.5 MB
__device__ __half g_whf16[H_ * H_];                  // 0.5 MB
// bf16 hi/lo operands for the output GEMM (3-term compensation)
__device__ __nv_bfloat16 g_qhi[B_ * T_ * H_],  g_qlo[B_ * T_ * H_];
__device__ __nv_bfloat16 g_wohi[H_ * 2 * H_],  g_wolo[H_ * 2 * H_];
__device__ __nv_bfloat16 g_chi[B_ * T_ * H_],  g_clo[B_ * T_ * H_];

// ---------------------------------------------------------------------------
__device__ __forceinline__ void bsplit(float x, __nv_bfloat16& hi, __nv_bfloat16& lo) {
    hi = __float2bfloat16(x);
    lo = __float2bfloat16(x - __bfloat162float(hi));
}
__device__ __forceinline__ uint32_t smem_u32(const void* p) {
    uint32_t a;
    asm("{ .reg .u64 t; cvta.to.shared.u64 t, %1; cvt.u32.u64 %0, t; }"
        : "=r"(a) : "l"(p));
    return a;
}
__device__ __forceinline__ void cpa16(uint32_t d, const void* s) {
    asm volatile("cp.async.cg.shared.global [%0], [%1], 16;" :: "r"(d), "l"(s));
}
#define CP_COMMIT() asm volatile("cp.async.commit_group;" ::: "memory")
#define CP_WAIT1()  asm volatile("cp.async.wait_group 1;" ::: "memory")
#define CP_WAIT0()  asm volatile("cp.async.wait_group 0;" ::: "memory")

__device__ __forceinline__ __half2 tanh2(__half2 x) {
    __half2 r;
    asm("tanh.approx.f16x2 %0, %1;"
        : "=r"(*reinterpret_cast<uint32_t*>(&r))
        : "r"(*reinterpret_cast<const uint32_t*>(&x)));
    return r;
}

// ---------------------------------------------------------------------------
// convert: query -> fp16 + bf16 hi/lo; enc/Ws/Wh -> fp16; Wout -> bf16 hi/lo.
// One float4 per thread. Segments (float4 units):
//   q 131072 | enc 262144 | ws 65536 | wh 65536 | wout 131072  = 655360
// ---------------------------------------------------------------------------
__global__ void __launch_bounds__(256) convert_kernel(
    const float* __restrict__ query, const float* __restrict__ enc,
    const float* __restrict__ W_s, const float* __restrict__ W_h,
    const float* __restrict__ W_out)
{
    const int i4 = blockIdx.x * 256 + threadIdx.x;

    if (i4 < 131072) {                     // query -> f16 AND bf16 hi/lo
        const float4 val = reinterpret_cast<const float4*>(query)[i4];
        const __half2 h0 = __floats2half2_rn(val.x, val.y);
        const __half2 h1 = __floats2half2_rn(val.z, val.w);
        uint2 st;
        st.x = *reinterpret_cast<const uint32_t*>(&h0);
        st.y = *reinterpret_cast<const uint32_t*>(&h1);
        reinterpret_cast<uint2*>(g_qf16)[i4] = st;
        union { __nv_bfloat16 h[4]; uint2 u; } ph, pl;
        bsplit(val.x, ph.h[0], pl.h[0]); bsplit(val.y, ph.h[1], pl.h[1]);
        bsplit(val.z, ph.h[2], pl.h[2]); bsplit(val.w, ph.h[3], pl.h[3]);
        reinterpret_cast<uint2*>(g_qhi)[i4] = ph.u;
        reinterpret_cast<uint2*>(g_qlo)[i4] = pl.u;
    } else if (i4 < 524288) {              // enc / W_s / W_h -> f16
        const float* src;
        __half* dst;
        int off;
        if (i4 < 393216)      { src = enc; dst = g_ef16;  off = i4 - 131072; }
        else if (i4 < 458752) { src = W_s; dst = g_wsf16; off = i4 - 393216; }
        else                  { src = W_h; dst = g_whf16; off = i4 - 458752; }
        const float4 val = reinterpret_cast<const float4*>(src)[off];
        const __half2 h0 = __floats2half2_rn(val.x, val.y);
        const __half2 h1 = __floats2half2_rn(val.z, val.w);
        uint2 st;
        st.x = *reinterpret_cast<const uint32_t*>(&h0);
        st.y = *reinterpret_cast<const uint32_t*>(&h1);
        reinterpret_cast<uint2*>(dst)[off] = st;
    } else {                               // W_out -> bf16 hi/lo
        const int off = i4 - 524288;
        const float4 val = reinterpret_cast<const float4*>(W_out)[off];
        union { __nv_bfloat16 h[4]; uint2 u; } ph, pl;
        bsplit(val.x, ph.h[0], pl.h[0]); bsplit(val.y, ph.h[1], pl.h[1]);
        bsplit(val.z, ph.h[2], pl.h[2]); bsplit(val.w, ph.h[3], pl.h[3]);
        reinterpret_cast<uint2*>(g_wohi)[off] = ph.u;
        reinterpret_cast<uint2*>(g_wolo)[off] = pl.u;
    }
}

// ---------------------------------------------------------------------------
// fp16 single-product split-K wmma GEMM (projections): fp32 partial output.
// Tile 64x64, 256 threads, 8 warps (warp tile 16x32), K-chunk 32, 2-stage.
// ---------------------------------------------------------------------------
#define FPITCH 40                           // halves; 80 B per row
#define FTILE_B (64 * FPITCH * 2)           // 5120 B per tile
#define FA_O 0
#define FB_O (FTILE_B)
#define FBUF_B (2 * FTILE_B)                // 10240 B per stage
#define FSMEM_BYTES (2 * FBUF_B)            // 20480 B

__device__ __forceinline__ void issue_chunk_f16(
    uint32_t sb,
    const __half* __restrict__ A, const __half* __restrict__ Bw,
    int ldb, int m0, int n0, int k0, int tid)
{
    const int row = tid >> 2, seg = tid & 3;           // 64 rows x 4 x 16B
    const uint32_t soff = (uint32_t)(row * (FPITCH * 2) + seg * 16);
    cpa16(sb + FA_O + soff, A + (size_t)(m0 + row) * H_ + k0 + seg * 8);
    cpa16(sb + FB_O + soff, Bw + (size_t)(n0 + row) * ldb + k0 + seg * 8);
}

__device__ __forceinline__ void gemm_f16_sk(
    char* smem,
    const __half* __restrict__ A, const __half* __restrict__ Bw,
    int ldb, float* __restrict__ Cpart,
    int m0, int n0, int kbeg, int nchunks)
{
    const int tid  = threadIdx.x;
    const int wid  = tid >> 5;
    const int m0w  = (wid >> 1) * 16;
    const int n0w  = (wid & 1) * 32;
    const uint32_t sb = smem_u32(smem);

    wmma::fragment<wmma::accumulator, 16, 16, 16, float> acc[2];
    wmma::fill_fragment(acc[0], 0.0f);
    wmma::fill_fragment(acc[1], 0.0f);

    issue_chunk_f16(sb, A, Bw, ldb, m0, n0, kbeg, tid);
    CP_COMMIT();

    #pragma unroll 1
    for (int it = 0; it < nchunks; ++it) {
        if (it + 1 < nchunks) {
            issue_chunk_f16(sb + ((it + 1) & 1) * FBUF_B, A, Bw, ldb,
                            m0, n0, kbeg + (it + 1) * 32, tid);
            CP_COMMIT();
            CP_WAIT1();
        } else {
            CP_WAIT0();
        }
        __syncthreads();

        const char* buf = smem + (it & 1) * FBUF_B;
        const __half* sA = reinterpret_cast<const __half*>(buf + FA_O);
        const __half* sB = reinterpret_cast<const __half*>(buf + FB_O);

        #pragma unroll
        for (int kf = 0; kf < 2; kf++) {
            const int ko = kf * 16;
            wmma::fragment<wmma::matrix_a, 16, 16, 16, __half, wmma::row_major> af;
            wmma::fragment<wmma::matrix_b, 16, 16, 16, __half, wmma::col_major> bf[2];
            wmma::load_matrix_sync(af, &sA[m0w * FPITCH + ko], FPITCH);
            #pragma unroll
            for (int ni = 0; ni < 2; ni++)
                wmma::load_matrix_sync(bf[ni], &sB[(n0w + 16 * ni) * FPITCH + ko], FPITCH);
            #pragma unroll
            for (int ni = 0; ni < 2; ni++)
                wmma::mma_sync(acc[ni], af, bf[ni], acc[ni]);
        }
        __syncthreads();
    }

    #pragma unroll
    for (int ni = 0; ni < 2; ni++)
        wmma::store_matrix_sync(
            &Cpart[(size_t)(m0 + m0w) * H_ + n0 + n0w + 16 * ni],
            acc[ni], H_, wmma::mem_row_major);
}

// proj: grid (8, 48, 2). y<16 -> qs partial; else hs partial. kz splits K=512 in 2.
__global__ void __launch_bounds__(256) proj_f16()
{
    __shared__ __align__(16) char smem[FSMEM_BYTES];
    const int n0 = blockIdx.x * 64;
    const int my = blockIdx.y;
    const int kz = blockIdx.z;
    const int kb = kz * 256;
    if (my < 16)
        gemm_f16_sk(smem, g_qf16, g_wsf16, H_, g_ppq[kz], my * 64, n0, kb, 8);
    else
        gemm_f16_sk(smem, g_ef16, g_whf16, H_, g_pph[kz], (my - 16) * 64, n0, kb, 8);
}

// preduce: hs = fp16(pph0+pph1)  (262144 float4s -> 1024 blocks)
__global__ void __launch_bounds__(256) preduce_kernel()
{
    const int j = blockIdx.x * 256 + threadIdx.x;
    const float4 a = reinterpret_cast<const float4*>(g_pph[0])[j];
    const float4 b = reinterpret_cast<const float4*>(g_pph[1])[j];
    const __half2 h0 = __floats2half2_rn(a.x + b.x, a.y + b.y);
    const __half2 h1 = __floats2half2_rn(a.z + b.z, a.w + b.w);
    uint2 st;
    st.x = *reinterpret_cast<const uint32_t*>(&h0);
    st.y = *reinterpret_cast<const uint32_t*>(&h1);
    reinterpret_cast<uint2*>(g_hsh)[j] = st;
}

// ---------------------------------------------------------------------------
// bf16 3-term compensated split-K wmma GEMM (output GEMM only).
// ---------------------------------------------------------------------------
#define PITCH 40
#define TILE_B (64 * PITCH * 2)
#define AHI_O 0
#define ALO_O (TILE_B)
#define BHI_O (2 * TILE_B)
#define BLO_O (3 * TILE_B)
#define BUF_B (4 * TILE_B)
#define SMEM_BYTES (2 * BUF_B)

__device__ __forceinline__ void issue_chunk(
    uint32_t sb,
    const __nv_bfloat16* __restrict__ Ahi, const __nv_bfloat16* __restrict__ Alo,
    const __nv_bfloat16* __restrict__ Bhi, const __nv_bfloat16* __restrict__ Blo,
    int ldb, int m0, int n0, int aoff, int boff, int tid)
{
    const int row = tid >> 2, seg = tid & 3;
    const uint32_t soff = (uint32_t)(row * (PITCH * 2) + seg * 16);
    const size_t ao = (size_t)(m0 + row) * H_ + aoff + seg * 8;
    const size_t bo = (size_t)(n0 + row) * ldb + boff + seg * 8;
    cpa16(sb + AHI_O + soff, Ahi + ao);
    cpa16(sb + ALO_O + soff, Alo + ao);
    cpa16(sb + BHI_O + soff, Bhi + bo);
    cpa16(sb + BLO_O + soff, Blo + bo);
}

__device__ __forceinline__ void gemm_sk(
    char* smem,
    const __nv_bfloat16* __restrict__ Ahi, const __nv_bfloat16* __restrict__ Alo,
    const __nv_bfloat16* __restrict__ Bhi, const __nv_bfloat16* __restrict__ Blo,
    int ldb, float* __restrict__ Cpart,
    int m0, int n0, int akbeg, int bkbeg, int nchunks)
{
    const int tid  = threadIdx.x;
    const int wid  = tid >> 5;
    const int m0w  = (wid >> 1) * 16;
    const int n0w  = (wid & 1) * 32;
    const uint32_t sb = smem_u32(smem);

    wmma::fragment<wmma::accumulator, 16, 16, 16, float> acc[2];
    wmma::fill_fragment(acc[0], 0.0f);
    wmma::fill_fragment(acc[1], 0.0f);

    issue_chunk(sb, Ahi, Alo, Bhi, Blo, ldb, m0, n0, akbeg, bkbeg, tid);
    CP_COMMIT();

    #pragma unroll 1
    for (int it = 0; it < nchunks; ++it) {
        if (it + 1 < nchunks) {
            issue_chunk(sb + ((it + 1) & 1) * BUF_B, Ahi, Alo, Bhi, Blo,
                        ldb, m0, n0, akbeg + (it + 1) * 32, bkbeg + (it + 1) * 32, tid);
            CP_COMMIT();
            CP_WAIT1();
        } else {
            CP_WAIT0();
        }
        __syncthreads();

        const char* buf = smem + (it & 1) * BUF_B;
        const __nv_bfloat16* sAhi = reinterpret_cast<const __nv_bfloat16*>(buf + AHI_O);
        const __nv_bfloat16* sAlo = reinterpret_cast<const __nv_bfloat16*>(buf + ALO_O);
        const __nv_bfloat16* sBhi = reinterpret_cast<const __nv_bfloat16*>(buf + BHI_O);
        const __nv_bfloat16* sBlo = reinterpret_cast<const __nv_bfloat16*>(buf + BLO_O);

        #pragma unroll
        for (int kf = 0; kf < 2; kf++) {
            const int ko = kf * 16;
            wmma::fragment<wmma::matrix_a, 16, 16, 16, __nv_bfloat16, wmma::row_major> ahi, alo;
            wmma::fragment<wmma::matrix_b, 16, 16, 16, __nv_bfloat16, wmma::col_major> bhi[2], blo[2];
            wmma::load_matrix_sync(ahi, &sAhi[m0w * PITCH + ko], PITCH);
            wmma::load_matrix_sync(alo, &sAlo[m0w * PITCH + ko], PITCH);
            #pragma unroll
            for (int ni = 0; ni < 2; ni++) {
                wmma::load_matrix_sync(bhi[ni], &sBhi[(n0w + 16 * ni) * PITCH + ko], PITCH);
                wmma::load_matrix_sync(blo[ni], &sBlo[(n0w + 16 * ni) * PITCH + ko], PITCH);
            }
            #pragma unroll
            for (int ni = 0; ni < 2; ni++) {
                wmma::mma_sync(acc[ni], ahi, bhi[ni], acc[ni]);
                wmma::mma_sync(acc[ni], ahi, blo[ni], acc[ni]);
                wmma::mma_sync(acc[ni], alo, bhi[ni], acc[ni]);
            }
        }
        __syncthreads();
    }

    #pragma unroll
    for (int ni = 0; ni < 2; ni++)
        wmma::store_matrix_sync(
            &Cpart[(size_t)(m0 + m0w) * H_ + n0 + n0w + 16 * ni],
            acc[ni], H_, wmma::mem_row_major);
}

// out: grid (8, 16, 4). kz<2 reads ctx, kz>=2 reads query (concat-aligned split-K).
__global__ void __launch_bounds__(256) out_wmma()
{
    __shared__ __align__(16) char smem[SMEM_BYTES];
    const int kz = blockIdx.z;
    const __nv_bfloat16* Ahi = (kz < 2) ? g_chi : g_qhi;
    const __nv_bfloat16* Alo = (kz < 2) ? g_clo : g_qlo;
    gemm_sk(smem, Ahi, Alo, g_wohi, g_wolo, 2 * H_,
            g_po[kz], blockIdx.y * 64, blockIdx.x * 64,
            (kz & 1) * 256, kz * 256, 8);
}

// oreduce: out = tanh(p0+p1+p2+p3 + bias)  (131072 float4s -> 512 blocks)
__global__ void __launch_bounds__(256) oreduce_kernel(
    const float* __restrict__ bias, float* __restrict__ out)
{
    const int i4 = blockIdx.x * 256 + threadIdx.x;
    const float4 p0 = reinterpret_cast<const float4*>(g_po[0])[i4];
    const float4 p1 = reinterpret_cast<const float4*>(g_po[1])[i4];
    const float4 p2 = reinterpret_cast<const float4*>(g_po[2])[i4];
    const float4 p3 = reinterpret_cast<const float4*>(g_po[3])[i4];
    const float4 bb = *reinterpret_cast<const float4*>(&bias[(i4 & 127) * 4]);
    float4 o;
    o.x = tanhf(p0.x + p1.x + p2.x + p3.x + bb.x);
    o.y = tanhf(p0.y + p1.y + p2.y + p3.y + bb.y);
    o.z = tanhf(p0.z + p1.z + p2.z + p3.z + bb.z);
    o.w = tanhf(p0.w + p1.w + p2.w + p3.w + bb.w);
    reinterpret_cast<float4*>(out)[i4] = o;
}

// ---------------------------------------------------------------------------
// Fused attention, TT=4, 512 threads, 256 blocks, 2 CTAs/SM. (R14 version)
// ---------------------------------------------------------------------------
#define TT 4
#define SC 16

__global__ void __launch_bounds__(512, 2) attn_kernel(
    const float* __restrict__ enc, const float* __restrict__ v,
    const int* __restrict__ lens)
{
    __shared__ __align__(16) __half sh_hs[2][SC * H_];   // 2 x 16 KB
    __shared__ float sh_sc[S_][TT];                      // 4 KB (transposed)
    __shared__ float sh_rsum[TT];

    const int b     = blockIdx.y;
    const int t0    = blockIdx.x * TT;
    const int tid   = threadIdx.x;
    const int lane  = tid & 31;
    const int wid   = tid >> 5;
    const int t_loc = wid >> 2;
    const int squad = wid & 3;

    const int len = lens[b];
    const int nch = (len + SC - 1) / SC;

    __half2 qh[8], vh[8];
    {
        const size_t ro = (size_t)(b * T_ + t0 + t_loc) * H_;
        #pragma unroll
        for (int c = 0; c < 2; c++) {
            #pragma unroll
            for (int k2 = 0; k2 < 2; k2++) {
                const int off = c * 256 + lane * 8 + k2 * 4;
                const float4 p0 = *reinterpret_cast<const float4*>(&g_ppq[0][ro + off]);
                const float4 p1 = *reinterpret_cast<const float4*>(&g_ppq[1][ro + off]);
                const float4 vv = *reinterpret_cast<const float4*>(&v[off]);
                qh[c * 4 + k2 * 2 + 0] = __floats2half2_rn(p0.x + p1.x, p0.y + p1.y);
                qh[c * 4 + k2 * 2 + 1] = __floats2half2_rn(p0.z + p1.z, p0.w + p1.w);
                vh[c * 4 + k2 * 2 + 0] = __floats2half2_rn(vv.x, vv.y);
                vh[c * 4 + k2 * 2 + 1] = __floats2half2_rn(vv.z, vv.w);
            }
        }
    }

    const __half* hsb = g_hsh + (size_t)b * S_ * H_;
    const float* encb = enc + (size_t)b * S_ * H_;

    uint4 r[2];
    #pragma unroll
    for (int q = 0; q < 2; q++)
        r[q] = reinterpret_cast<const uint4*>(hsb)[q * 512 + tid];
    #pragma unroll
    for (int q = 0; q < 2; q++)
        reinterpret_cast<uint4*>(&sh_hs[0][0])[q * 512 + tid] = r[q];

    #pragma unroll 1
    for (int it = 0; it < nch; ++it) {
        if (it + 1 < nch) {
            const uint4* nxt = reinterpret_cast<const uint4*>(hsb + (size_t)(it + 1) * SC * H_);
            #pragma unroll
            for (int q = 0; q < 2; q++)
                r[q] = nxt[q * 512 + tid];
        }
        __syncthreads();

        const __half* base = sh_hs[it & 1];
        const int s0 = it * SC;
        #pragma unroll
        for (int i = 0; i < SC / 4; i++) {
            const int ro = squad * (SC / 4) + i;
            const uint4* hrow = reinterpret_cast<const uint4*>(&base[ro * H_]);
            __half2 accA = __float2half2_rn(0.0f);
            __half2 accB = __float2half2_rn(0.0f);
            #pragma unroll
            for (int c = 0; c < 2; c++) {
                const uint4 hv = hrow[c * 32 + lane];
                const __half2 h0 = *reinterpret_cast<const __half2*>(&hv.x);
                const __half2 h1 = *reinterpret_cast<const __half2*>(&hv.y);
                const __half2 h2 = *reinterpret_cast<const __half2*>(&hv.z);
                const __half2 h3 = *reinterpret_cast<const __half2*>(&hv.w);
                accA = __hfma2(tanh2(__hadd2(qh[c * 4 + 0], h0)), vh[c * 4 + 0], accA);
                accB = __hfma2(tanh2(__hadd2(qh[c * 4 + 1], h1)), vh[c * 4 + 1], accB);
                accA = __hfma2(tanh2(__hadd2(qh[c * 4 + 2], h2)), vh[c * 4 + 2], accA);
                accB = __hfma2(tanh2(__hadd2(qh[c * 4 + 3], h3)), vh[c * 4 + 3], accB);
            }
            const float2 fA = __half22float2(accA);
            const float2 fB = __half22float2(accB);
            float acc = (fA.x + fA.y) + (fB.x + fB.y);
            acc += __shfl_xor_sync(0xffffffffu, acc, 16);
            acc += __shfl_xor_sync(0xffffffffu, acc, 8);
            acc += __shfl_xor_sync(0xffffffffu, acc, 4);
            acc += __shfl_xor_sync(0xffffffffu, acc, 2);
            acc += __shfl_xor_sync(0xffffffffu, acc, 1);
            if (lane == 0) sh_sc[s0 + ro][t_loc] = acc;
        }

        if (it + 1 < nch) {
            uint4* dst = reinterpret_cast<uint4*>(&sh_hs[(it + 1) & 1][0]);
            #pragma unroll
            for (int q = 0; q < 2; q++)
                dst[q * 512 + tid] = r[q];
        }
    }
    __syncthreads();

    if (wid < TT) {
        const int t = wid;
        float vals[S_ / 32];
        float m = -1e30f;
        #pragma unroll
        for (int i = 0; i < S_ / 32; i++) {
            const int s = lane + 32 * i;
            const float sc = (s < len) ? sh_sc[s][t] : -1e30f;
            vals[i] = sc;
            m = fmaxf(m, sc);
        }
        #pragma unroll
        for (int o = 16; o; o >>= 1) m = fmaxf(m, __shfl_xor_sync(0xffffffffu, m, o));
        float sum = 0.f;
        #pragma unroll
        for (int i = 0; i < S_ / 32; i++) {
            const int s = lane + 32 * i;
            const float e = (s < len) ? __expf(vals[i] - m) : 0.f;
            sh_sc[s][t] = e;
            sum += e;
        }
        #pragma unroll
        for (int o = 16; o; o >>= 1) sum += __shfl_xor_sync(0xffffffffu, sum, o);
        if (lane == 0) sh_rsum[t] = 1.0f / sum;
    }
    __syncthreads();

    const int g  = tid >> 7;
    const int c4 = tid & 127;
    const int sbeg = (g * len) >> 2;
    const int send = ((g + 1) * len) >> 2;

    float4 acc4[TT];
    #pragma unroll
    for (int t = 0; t < TT; t++) acc4[t] = make_float4(0.f, 0.f, 0.f, 0.f);

    #pragma unroll 4
    for (int s = sbeg; s < send; s++) {
        const float4 e4 = *reinterpret_cast<const float4*>(&encb[(size_t)s * H_ + c4 * 4]);
        const float4 w4 = *reinterpret_cast<const float4*>(&sh_sc[s][0]);
        acc4[0].x = fmaf(w4.x, e4.x, acc4[0].x);
        acc4[0].y = fmaf(w4.x, e4.y, acc4[0].y);
        acc4[0].z = fmaf(w4.x, e4.z, acc4[0].z);
        acc4[0].w = fmaf(w4.x, e4.w, acc4[0].w);
        acc4[1].x = fmaf(w4.y, e4.x, acc4[1].x);
        acc4[1].y = fmaf(w4.y, e4.y, acc4[1].y);
        acc4[1].z = fmaf(w4.y, e4.z, acc4[1].z);
        acc4[1].w = fmaf(w4.y, e4.w, acc4[1].w);
        acc4[2].x = fmaf(w4.z, e4.x, acc4[2].x);
        acc4[2].y = fmaf(w4.z, e4.y, acc4[2].y);
        acc4[2].z = fmaf(w4.z, e4.z, acc4[2].z);
        acc4[2].w = fmaf(w4.z, e4.w, acc4[2].w);
        acc4[3].x = fmaf(w4.w, e4.x, acc4[3].x);
        acc4[3].y = fmaf(w4.w, e4.y, acc4[3].y);
        acc4[3].z = fmaf(w4.w, e4.z, acc4[3].z);
        acc4[3].w = fmaf(w4.w, e4.w, acc4[3].w);
    }

    float* bufA = reinterpret_cast<float*>(&sh_hs[0][0]);
    float* bufB = reinterpret_cast<float*>(&sh_hs[1][0]);
    if (g == 1) {
        #pragma unroll
        for (int t = 0; t < TT; t++)
            *reinterpret_cast<float4*>(&bufA[(t * 128 + c4) * 4]) = acc4[t];
    }
    if (g == 3) {
        #pragma unroll
        for (int t = 0; t < TT; t++)
            *reinterpret_cast<float4*>(&bufB[(t * 128 + c4) * 4]) = acc4[t];
    }
    __syncthreads();
    if (g == 0) {
        #pragma unroll
        for (int t = 0; t < TT; t++) {
            const float4 p = *reinterpret_cast<const float4*>(&bufA[(t * 128 + c4) * 4]);
            acc4[t].x += p.x; acc4[t].y += p.y; acc4[t].z += p.z; acc4[t].w += p.w;
        }
    }
    if (g == 2) {
        #pragma unroll
        for (int t = 0; t < TT; t++) {
            const float4 p = *reinterpret_cast<const float4*>(&bufB[(t * 128 + c4) * 4]);
            acc4[t].x += p.x; acc4[t].y += p.y; acc4[t].z += p.z; acc4[t].w += p.w;
            *reinterpret_cast<float4*>(&bufB[(t * 128 + c4) * 4]) = acc4[t];
        }
    }
    __syncthreads();
    if (g == 0) {
        #pragma unroll
        for (int t = 0; t < TT; t++) {
            const float4 p = *reinterpret_cast<const float4*>(&bufB[(t * 128 + c4) * 4]);
            const float rs = sh_rsum[t];
            float4 o;
            o.x = (acc4[t].x + p.x) * rs;
            o.y = (acc4[t].y + p.y) * rs;
            o.z = (acc4[t].z + p.z) * rs;
            o.w = (acc4[t].w + p.w) * rs;
            union { __nv_bfloat16 h[4]; uint2 u; } ph, pl;
            bsplit(o.x, ph.h[0], pl.h[0]); bsplit(o.y, ph.h[1], pl.h[1]);
            bsplit(o.z, ph.h[2], pl.h[2]); bsplit(o.w, ph.h[3], pl.h[3]);
            const size_t off = (size_t)(b * T_ + t0 + t) * H_ + c4 * 4;
            *reinterpret_cast<uint2*>(&g_chi[off]) = ph.u;
            *reinterpret_cast<uint2*>(&g_clo[off]) = pl.u;
        }
    }
}

// ---------------------------------------------------------------------------
extern "C" void kernel_launch(void* const* d_in, const int* in_sizes, int n_in,
                              void* d_out, int out_size)
{
    const float* query = (const float*)d_in[0];
    const float* enc   = (const float*)d_in[1];
    const int*   lens  = (const int*)d_in[2];
    const float* W_s   = (const float*)d_in[3];
    const float* W_h   = (const float*)d_in[4];
    const float* v     = (const float*)d_in[5];
    const float* W_out = (const float*)d_in[6];
    const float* b_out = (const float*)d_in[7];
    float* out = (float*)d_out;

    convert_kernel<<<2560, 256>>>(query, enc, W_s, W_h, W_out);
    proj_f16<<<dim3(8, 48, 2), 256>>>();
    preduce_kernel<<<1024, 256>>>();
    attn_kernel<<<dim3(T_ / TT, B_), 512>>>(enc, v, lens);
    out_wmma<<<dim3(8, 16, 4), 256>>>();
    oreduce_kernel<<<512, 256>>>(b_out, out);
}

// round 16
// speedup vs baseline: 1.3650x; 1.1542x over previous
#include <cuda_runtime.h>
#include <cuda_fp16.h>
#include <mma.h>
#include <math.h>
#include <stdint.h>

using namespace nvcuda;

#define B_ 8
#define T_ 128
#define S_ 256
#define H_ 512

// scratch
__device__ float  g_qs[B_ * T_ * H_];                // 2 MB  qs fp32
__device__ __half g_hsh[B_ * S_ * H_];               // 2 MB  hs fp16
__device__ float  g_po[4][B_ * T_ * H_];             // 8 MB  out split-K partials
// fp16 operands
__device__ __half g_qf16[B_ * T_ * H_];              // 1 MB
__device__ __half g_ef16[B_ * S_ * H_];              // 2 MB
__device__ __half g_wsf16[H_ * H_];                  // 0.5 MB
__device__ __half g_whf16[H_ * H_];                  // 0.5 MB
__device__ __half g_wof16[H_ * 2 * H_];              // 1 MB
__device__ __half g_cf16[B_ * T_ * H_];              // 1 MB  ctx fp16

// ---------------------------------------------------------------------------
__device__ __forceinline__ uint32_t smem_u32(const void* p) {
    uint32_t a;
    asm("{ .reg .u64 t; cvta.to.shared.u64 t, %1; cvt.u32.u64 %0, t; }"
        : "=r"(a) : "l"(p));
    return a;
}
__device__ __forceinline__ void cpa16(uint32_t d, const void* s) {
    asm volatile("cp.async.cg.shared.global [%0], [%1], 16;" :: "r"(d), "l"(s));
}
#define CP_COMMIT() asm volatile("cp.async.commit_group;" ::: "memory")
#define CP_WAIT1()  asm volatile("cp.async.wait_group 1;" ::: "memory")
#define CP_WAIT0()  asm volatile("cp.async.wait_group 0;" ::: "memory")

__device__ __forceinline__ __half2 tanh2(__half2 x) {
    __half2 r;
    asm("tanh.approx.f16x2 %0, %1;"
        : "=r"(*reinterpret_cast<uint32_t*>(&r))
        : "r"(*reinterpret_cast<const uint32_t*>(&x)));
    return r;
}
__device__ __forceinline__ uint2 pack_f16x4(float x, float y, float z, float w) {
    const __half2 h0 = __floats2half2_rn(x, y);
    const __half2 h1 = __floats2half2_rn(z, w);
    uint2 st;
    st.x = *reinterpret_cast<const uint32_t*>(&h0);
    st.y = *reinterpret_cast<const uint32_t*>(&h1);
    return st;
}

// ---------------------------------------------------------------------------
// convert: everything to fp16. One float4 per thread. Segments (float4 units):
//   q 131072 | enc 262144 | ws 65536 | wh 65536 | wout 131072  = 655360
// ---------------------------------------------------------------------------
__global__ void __launch_bounds__(256) convert_kernel(
    const float* __restrict__ query, const float* __restrict__ enc,
    const float* __restrict__ W_s, const float* __restrict__ W_h,
    const float* __restrict__ W_out)
{
    const int i4 = blockIdx.x * 256 + threadIdx.x;
    const float* src;
    __half* dst;
    int off;
    if (i4 < 131072)      { src = query; dst = g_qf16;  off = i4; }
    else if (i4 < 393216) { src = enc;   dst = g_ef16;  off = i4 - 131072; }
    else if (i4 < 458752) { src = W_s;   dst = g_wsf16; off = i4 - 393216; }
    else if (i4 < 524288) { src = W_h;   dst = g_whf16; off = i4 - 458752; }
    else                  { src = W_out; dst = g_wof16; off = i4 - 524288; }

    const float4 v = reinterpret_cast<const float4*>(src)[off];
    reinterpret_cast<uint2*>(dst)[off] = pack_f16x4(v.x, v.y, v.z, v.w);
}

// ---------------------------------------------------------------------------
// fp16 single-product wmma GEMM. Tile 64x64, 256 threads, 8 warps
// (warp tile 16x32), K-chunk 32, 2-stage cp.async pipeline.
// F16OUT: epilogue converts to fp16 (pitch H_); else fp32 direct store.
// ---------------------------------------------------------------------------
#define FPITCH 40                           // halves; 80 B per row
#define FTILE_B (64 * FPITCH * 2)           // 5120 B per tile
#define FA_O 0
#define FB_O (FTILE_B)
#define FBUF_B (2 * FTILE_B)                // 10240 B per stage
#define FSMEM_BYTES (2 * FBUF_B)            // 20480 B (>= 16KB f32 stage)

__device__ __forceinline__ void issue_chunk_f16(
    uint32_t sb,
    const __half* __restrict__ A, const __half* __restrict__ Bw,
    int ldb, int m0, int n0, int ak, int bk, int tid)
{
    const int row = tid >> 2, seg = tid & 3;           // 64 rows x 4 x 16B
    const uint32_t soff = (uint32_t)(row * (FPITCH * 2) + seg * 16);
    cpa16(sb + FA_O + soff, A + (size_t)(m0 + row) * H_ + ak + seg * 8);
    cpa16(sb + FB_O + soff, Bw + (size_t)(n0 + row) * ldb + bk + seg * 8);
}

template <bool F16OUT>
__device__ __forceinline__ void gemm_f16(
    char* smem,
    const __half* __restrict__ A, const __half* __restrict__ Bw,
    int ldb, float* __restrict__ Cf32, __half* __restrict__ Cf16,
    int m0, int n0, int akbeg, int bkbeg, int nchunks)
{
    const int tid  = threadIdx.x;
    const int wid  = tid >> 5;
    const int m0w  = (wid >> 1) * 16;
    const int n0w  = (wid & 1) * 32;
    const uint32_t sb = smem_u32(smem);

    wmma::fragment<wmma::accumulator, 16, 16, 16, float> acc[2];
    wmma::fill_fragment(acc[0], 0.0f);
    wmma::fill_fragment(acc[1], 0.0f);

    issue_chunk_f16(sb, A, Bw, ldb, m0, n0, akbeg, bkbeg, tid);
    CP_COMMIT();

    #pragma unroll 1
    for (int it = 0; it < nchunks; ++it) {
        if (it + 1 < nchunks) {
            issue_chunk_f16(sb + ((it + 1) & 1) * FBUF_B, A, Bw, ldb, m0, n0,
                            akbeg + (it + 1) * 32, bkbeg + (it + 1) * 32, tid);
            CP_COMMIT();
            CP_WAIT1();
        } else {
            CP_WAIT0();
        }
        __syncthreads();

        const char* buf = smem + (it & 1) * FBUF_B;
        const __half* sA = reinterpret_cast<const __half*>(buf + FA_O);
        const __half* sB = reinterpret_cast<const __half*>(buf + FB_O);

        #pragma unroll
        for (int kf = 0; kf < 2; kf++) {
            const int ko = kf * 16;
            wmma::fragment<wmma::matrix_a, 16, 16, 16, __half, wmma::row_major> af;
            wmma::fragment<wmma::matrix_b, 16, 16, 16, __half, wmma::col_major> bf[2];
            wmma::load_matrix_sync(af, &sA[m0w * FPITCH + ko], FPITCH);
            #pragma unroll
            for (int ni = 0; ni < 2; ni++)
                wmma::load_matrix_sync(bf[ni], &sB[(n0w + 16 * ni) * FPITCH + ko], FPITCH);
            #pragma unroll
            for (int ni = 0; ni < 2; ni++)
                wmma::mma_sync(acc[ni], af, bf[ni], acc[ni]);
        }
        __syncthreads();
    }

    if (!F16OUT) {
        #pragma unroll
        for (int ni = 0; ni < 2; ni++)
            wmma::store_matrix_sync(
                &Cf32[(size_t)(m0 + m0w) * H_ + n0 + n0w + 16 * ni],
                acc[ni], H_, wmma::mem_row_major);
    } else {
        // stage fp32 in smem (16 KB <= pipeline smem), then convert to fp16
        float* stage = reinterpret_cast<float*>(smem);
        #pragma unroll
        for (int ni = 0; ni < 2; ni++)
            wmma::store_matrix_sync(&stage[m0w * 64 + n0w + 16 * ni],
                                    acc[ni], 64, wmma::mem_row_major);
        __syncthreads();
        const int row = tid >> 2;
        const int cq  = (tid & 3) * 16;
        const float4 s0 = *reinterpret_cast<const float4*>(&stage[row * 64 + cq + 0]);
        const float4 s1 = *reinterpret_cast<const float4*>(&stage[row * 64 + cq + 4]);
        const float4 s2 = *reinterpret_cast<const float4*>(&stage[row * 64 + cq + 8]);
        const float4 s3 = *reinterpret_cast<const float4*>(&stage[row * 64 + cq + 12]);
        __half* drow = Cf16 + (size_t)(m0 + row) * H_ + n0 + cq;
        uint4 o0, o1;
        *reinterpret_cast<uint2*>(&o0.x) = pack_f16x4(s0.x, s0.y, s0.z, s0.w);
        *reinterpret_cast<uint2*>(&o0.z) = pack_f16x4(s1.x, s1.y, s1.z, s1.w);
        *reinterpret_cast<uint2*>(&o1.x) = pack_f16x4(s2.x, s2.y, s2.z, s2.w);
        *reinterpret_cast<uint2*>(&o1.z) = pack_f16x4(s3.x, s3.y, s3.z, s3.w);
        *reinterpret_cast<uint4*>(drow) = o0;
        *reinterpret_cast<uint4*>(drow + 8) = o1;
    }
}

// proj: grid (8, 48). y<16 -> qs fp32 (full K); else hs fp16 (full K).
__global__ void __launch_bounds__(256) proj_f16()
{
    __shared__ __align__(16) char smem[FSMEM_BYTES];
    const int n0 = blockIdx.x * 64;
    const int my = blockIdx.y;
    if (my < 16)
        gemm_f16<false>(smem, g_qf16, g_wsf16, H_, g_qs, nullptr,
                        my * 64, n0, 0, 0, 16);
    else
        gemm_f16<true>(smem, g_ef16, g_whf16, H_, nullptr, g_hsh,
                       (my - 16) * 64, n0, 0, 0, 16);
}

// out: grid (8, 16, 4). kz<2 reads ctx f16, kz>=2 reads query f16.
__global__ void __launch_bounds__(256) out_f16()
{
    __shared__ __align__(16) char smem[FSMEM_BYTES];
    const int kz = blockIdx.z;
    const __half* A = (kz < 2) ? g_cf16 : g_qf16;
    gemm_f16<false>(smem, A, g_wof16, 2 * H_, g_po[kz], nullptr,
                    blockIdx.y * 64, blockIdx.x * 64,
                    (kz & 1) * 256, kz * 256, 8);
}

// oreduce: out = tanh(p0+p1+p2+p3 + bias)  (131072 float4s -> 512 blocks)
__global__ void __launch_bounds__(256) oreduce_kernel(
    const float* __restrict__ bias, float* __restrict__ out)
{
    const int i4 = blockIdx.x * 256 + threadIdx.x;
    const float4 p0 = reinterpret_cast<const float4*>(g_po[0])[i4];
    const float4 p1 = reinterpret_cast<const float4*>(g_po[1])[i4];
    const float4 p2 = reinterpret_cast<const float4*>(g_po[2])[i4];
    const float4 p3 = reinterpret_cast<const float4*>(g_po[3])[i4];
    const float4 bb = *reinterpret_cast<const float4*>(&bias[(i4 & 127) * 4]);
    float4 o;
    o.x = tanhf(p0.x + p1.x + p2.x + p3.x + bb.x);
    o.y = tanhf(p0.y + p1.y + p2.y + p3.y + bb.y);
    o.z = tanhf(p0.z + p1.z + p2.z + p3.z + bb.z);
    o.w = tanhf(p0.w + p1.w + p2.w + p3.w + bb.w);
    reinterpret_cast<float4*>(out)[i4] = o;
}

// ---------------------------------------------------------------------------
// Fused attention, TT=4, 512 threads, 256 blocks, 2 CTAs/SM. (R14 structure)
// q read from fp32 g_qs; ctx emitted as plain fp16 (g_cf16).
// ---------------------------------------------------------------------------
#define TT 4
#define SC 16

__global__ void __launch_bounds__(512, 2) attn_kernel(
    const float* __restrict__ enc, const float* __restrict__ v,
    const int* __restrict__ lens)
{
    __shared__ __align__(16) __half sh_hs[2][SC * H_];   // 2 x 16 KB
    __shared__ float sh_sc[S_][TT];                      // 4 KB (transposed)
    __shared__ float sh_rsum[TT];

    const int b     = blockIdx.y;
    const int t0    = blockIdx.x * TT;
    const int tid   = threadIdx.x;
    const int lane  = tid & 31;
    const int wid   = tid >> 5;
    const int t_loc = wid >> 2;
    const int squad = wid & 3;

    const int len = lens[b];
    const int nch = (len + SC - 1) / SC;

    __half2 qh[8], vh[8];
    {
        const size_t ro = (size_t)(b * T_ + t0 + t_loc) * H_;
        #pragma unroll
        for (int c = 0; c < 2; c++) {
            #pragma unroll
            for (int k2 = 0; k2 < 2; k2++) {
                const int off = c * 256 + lane * 8 + k2 * 4;
                const float4 p0 = *reinterpret_cast<const float4*>(&g_qs[ro + off]);
                const float4 vv = *reinterpret_cast<const float4*>(&v[off]);
                qh[c * 4 + k2 * 2 + 0] = __floats2half2_rn(p0.x, p0.y);
                qh[c * 4 + k2 * 2 + 1] = __floats2half2_rn(p0.z, p0.w);
                vh[c * 4 + k2 * 2 + 0] = __floats2half2_rn(vv.x, vv.y);
                vh[c * 4 + k2 * 2 + 1] = __floats2half2_rn(vv.z, vv.w);
            }
        }
    }

    const __half* hsb = g_hsh + (size_t)b * S_ * H_;
    const float* encb = enc + (size_t)b * S_ * H_;

    uint4 r[2];
    #pragma unroll
    for (int q = 0; q < 2; q++)
        r[q] = reinterpret_cast<const uint4*>(hsb)[q * 512 + tid];
    #pragma unroll
    for (int q = 0; q < 2; q++)
        reinterpret_cast<uint4*>(&sh_hs[0][0])[q * 512 + tid] = r[q];

    #pragma unroll 1
    for (int it = 0; it < nch; ++it) {
        if (it + 1 < nch) {
            const uint4* nxt = reinterpret_cast<const uint4*>(hsb + (size_t)(it + 1) * SC * H_);
            #pragma unroll
            for (int q = 0; q < 2; q++)
                r[q] = nxt[q * 512 + tid];
        }
        __syncthreads();

        const __half* base = sh_hs[it & 1];
        const int s0 = it * SC;
        #pragma unroll
        for (int i = 0; i < SC / 4; i++) {
            const int ro = squad * (SC / 4) + i;
            const uint4* hrow = reinterpret_cast<const uint4*>(&base[ro * H_]);
            __half2 accA = __float2half2_rn(0.0f);
            __half2 accB = __float2half2_rn(0.0f);
            #pragma unroll
            for (int c = 0; c < 2; c++) {
                const uint4 hv = hrow[c * 32 + lane];
                const __half2 h0 = *reinterpret_cast<const __half2*>(&hv.x);
                const __half2 h1 = *reinterpret_cast<const __half2*>(&hv.y);
                const __half2 h2 = *reinterpret_cast<const __half2*>(&hv.z);
                const __half2 h3 = *reinterpret_cast<const __half2*>(&hv.w);
                accA = __hfma2(tanh2(__hadd2(qh[c * 4 + 0], h0)), vh[c * 4 + 0], accA);
                accB = __hfma2(tanh2(__hadd2(qh[c * 4 + 1], h1)), vh[c * 4 + 1], accB);
                accA = __hfma2(tanh2(__hadd2(qh[c * 4 + 2], h2)), vh[c * 4 + 2], accA);
                accB = __hfma2(tanh2(__hadd2(qh[c * 4 + 3], h3)), vh[c * 4 + 3], accB);
            }
            const float2 fA = __half22float2(accA);
            const float2 fB = __half22float2(accB);
            float acc = (fA.x + fA.y) + (fB.x + fB.y);
            acc += __shfl_xor_sync(0xffffffffu, acc, 16);
            acc += __shfl_xor_sync(0xffffffffu, acc, 8);
            acc += __shfl_xor_sync(0xffffffffu, acc, 4);
            acc += __shfl_xor_sync(0xffffffffu, acc, 2);
            acc += __shfl_xor_sync(0xffffffffu, acc, 1);
            if (lane == 0) sh_sc[s0 + ro][t_loc] = acc;
        }

        if (it + 1 < nch) {
            uint4* dst = reinterpret_cast<uint4*>(&sh_hs[(it + 1) & 1][0]);
            #pragma unroll
            for (int q = 0; q < 2; q++)
                dst[q * 512 + tid] = r[q];
        }
    }
    __syncthreads();

    if (wid < TT) {
        const int t = wid;
        float vals[S_ / 32];
        float m = -1e30f;
        #pragma unroll
        for (int i = 0; i < S_ / 32; i++) {
            const int s = lane + 32 * i;
            const float sc = (s < len) ? sh_sc[s][t] : -1e30f;
            vals[i] = sc;
            m = fmaxf(m, sc);
        }
        #pragma unroll
        for (int o = 16; o; o >>= 1) m = fmaxf(m, __shfl_xor_sync(0xffffffffu, m, o));
        float sum = 0.f;
        #pragma unroll
        for (int i = 0; i < S_ / 32; i++) {
            const int s = lane + 32 * i;
            const float e = (s < len) ? __expf(vals[i] - m) : 0.f;
            sh_sc[s][t] = e;
            sum += e;
        }
        #pragma unroll
        for (int o = 16; o; o >>= 1) sum += __shfl_xor_sync(0xffffffffu, sum, o);
        if (lane == 0) sh_rsum[t] = 1.0f / sum;
    }
    __syncthreads();

    const int g  = tid >> 7;
    const int c4 = tid & 127;
    const int sbeg = (g * len) >> 2;
    const int send = ((g + 1) * len) >> 2;

    float4 acc4[TT];
    #pragma unroll
    for (int t = 0; t < TT; t++) acc4[t] = make_float4(0.f, 0.f, 0.f, 0.f);

    #pragma unroll 4
    for (int s = sbeg; s < send; s++) {
        const float4 e4 = *reinterpret_cast<const float4*>(&encb[(size_t)s * H_ + c4 * 4]);
        const float4 w4 = *reinterpret_cast<const float4*>(&sh_sc[s][0]);
        acc4[0].x = fmaf(w4.x, e4.x, acc4[0].x);
        acc4[0].y = fmaf(w4.x, e4.y, acc4[0].y);
        acc4[0].z = fmaf(w4.x, e4.z, acc4[0].z);
        acc4[0].w = fmaf(w4.x, e4.w, acc4[0].w);
        acc4[1].x = fmaf(w4.y, e4.x, acc4[1].x);
        acc4[1].y = fmaf(w4.y, e4.y, acc4[1].y);
        acc4[1].z = fmaf(w4.y, e4.z, acc4[1].z);
        acc4[1].w = fmaf(w4.y, e4.w, acc4[1].w);
        acc4[2].x = fmaf(w4.z, e4.x, acc4[2].x);
        acc4[2].y = fmaf(w4.z, e4.y, acc4[2].y);
        acc4[2].z = fmaf(w4.z, e4.z, acc4[2].z);
        acc4[2].w = fmaf(w4.z, e4.w, acc4[2].w);
        acc4[3].x = fmaf(w4.w, e4.x, acc4[3].x);
        acc4[3].y = fmaf(w4.w, e4.y, acc4[3].y);
        acc4[3].z = fmaf(w4.w, e4.z, acc4[3].z);
        acc4[3].w = fmaf(w4.w, e4.w, acc4[3].w);
    }

    float* bufA = reinterpret_cast<float*>(&sh_hs[0][0]);
    float* bufB = reinterpret_cast<float*>(&sh_hs[1][0]);
    if (g == 1) {
        #pragma unroll
        for (int t = 0; t < TT; t++)
            *reinterpret_cast<float4*>(&bufA[(t * 128 + c4) * 4]) = acc4[t];
    }
    if (g == 3) {
        #pragma unroll
        for (int t = 0; t < TT; t++)
            *reinterpret_cast<float4*>(&bufB[(t * 128 + c4) * 4]) = acc4[t];
    }
    __syncthreads();
    if (g == 0) {
        #pragma unroll
        for (int t = 0; t < TT; t++) {
            const float4 p = *reinterpret_cast<const float4*>(&bufA[(t * 128 + c4) * 4]);
            acc4[t].x += p.x; acc4[t].y += p.y; acc4[t].z += p.z; acc4[t].w += p.w;
        }
    }
    if (g == 2) {
        #pragma unroll
        for (int t = 0; t < TT; t++) {
            const float4 p = *reinterpret_cast<const float4*>(&bufB[(t * 128 + c4) * 4]);
            acc4[t].x += p.x; acc4[t].y += p.y; acc4[t].z += p.z; acc4[t].w += p.w;
            *reinterpret_cast<float4*>(&bufB[(t * 128 + c4) * 4]) = acc4[t];
        }
    }
    __syncthreads();
    if (g == 0) {
        #pragma unroll
        for (int t = 0; t < TT; t++) {
            const float4 p = *reinterpret_cast<const float4*>(&bufB[(t * 128 + c4) * 4]);
            const float rs = sh_rsum[t];
            const size_t off = (size_t)(b * T_ + t0 + t) * H_ + c4 * 4;
            *reinterpret_cast<uint2*>(&g_cf16[off]) =
                pack_f16x4((acc4[t].x + p.x) * rs, (acc4[t].y + p.y) * rs,
                           (acc4[t].z + p.z) * rs, (acc4[t].w + p.w) * rs);
        }
    }
}

// ---------------------------------------------------------------------------
extern "C" void kernel_launch(void* const* d_in, const int* in_sizes, int n_in,
                              void* d_out, int out_size)
{
    const float* query = (const float*)d_in[0];
    const float* enc   = (const float*)d_in[1];
    const int*   lens  = (const int*)d_in[2];
    const float* W_s   = (const float*)d_in[3];
    const float* W_h   = (const float*)d_in[4];
    const float* v     = (const float*)d_in[5];
    const float* W_out = (const float*)d_in[6];
    const float* b_out = (const float*)d_in[7];
    float* out = (float*)d_out;

    convert_kernel<<<2560, 256>>>(query, enc, W_s, W_h, W_out);
    proj_f16<<<dim3(8, 48), 256>>>();
    attn_kernel<<<dim3(T_ / TT, B_), 512>>>(enc, v, lens);
    out_f16<<<dim3(8, 16, 4), 256>>>();
    oreduce_kernel<<<512, 256>>>(b_out, out);
}